// round 12
// baseline (speedup 1.0000x reference)
#include <cuda_runtime.h>
#include <cuda_fp16.h>
#include <cstdint>

#define N_NODES 50000
#define N_EDGES 625000
#define D       128
#define CAP     64          // bucket capacity per node (max degree ~45 expected)

// ---- scratch (__device__ globals; allocation-free requirement) ----
__device__ int2   g_bucket[N_NODES * CAP]; // 25.6 MB
__device__ int    g_cnt[N_NODES];
__device__ __half g_wt[D * D];             // W transposed fp16: [k][n]

// ---------------------------------------------------------------------------
// 1) prep: zero cnt + transpose W to fp16
// ---------------------------------------------------------------------------
__global__ void prep_kernel(const float* __restrict__ W) {
    int i = blockIdx.x * blockDim.x + threadIdx.x;
    int stride = gridDim.x * blockDim.x;
    for (int idx = i; idx < N_NODES; idx += stride) g_cnt[idx] = 0;
    for (int idx = i; idx < D * D; idx += stride) {
        int n = idx / D, k = idx % D;        // W row-major [n][k]
        g_wt[k * D + n] = __float2half_rn(W[idx]);
    }
}

// ---------------------------------------------------------------------------
// 2) fill buckets: 4 edges per thread (vectorized index loads)
// ---------------------------------------------------------------------------
__global__ void __launch_bounds__(256) fill_kernel(
    const float* __restrict__ d, const int* __restrict__ src,
    const int* __restrict__ dst)
{
    int i = blockIdx.x * blockDim.x + threadIdx.x;
    if (i * 4 >= N_EDGES) return;
    int4   s4 = __ldg(reinterpret_cast<const int4*>(src) + i);
    int4   t4 = __ldg(reinterpret_cast<const int4*>(dst) + i);
    float4 d4 = __ldg(reinterpret_cast<const float4*>(d) + i);

    int p;
    p = atomicAdd(&g_cnt[t4.x], 1);
    if (p < CAP) g_bucket[t4.x * CAP + p] = make_int2(s4.x, __float_as_int(1.0f - d4.x));
    p = atomicAdd(&g_cnt[t4.y], 1);
    if (p < CAP) g_bucket[t4.y * CAP + p] = make_int2(s4.y, __float_as_int(1.0f - d4.y));
    p = atomicAdd(&g_cnt[t4.z], 1);
    if (p < CAP) g_bucket[t4.z * CAP + p] = make_int2(s4.z, __float_as_int(1.0f - d4.z));
    p = atomicAdd(&g_cnt[t4.w], 1);
    if (p < CAP) g_bucket[t4.w * CAP + p] = make_int2(s4.w, __float_as_int(1.0f - d4.w));
}

// ---------------------------------------------------------------------------
// 3) FUSED gather + GEMM + bias + ReLU
//    Phase A: each warp gathers 16 nodes -> fp16 x rows straight into smem.
//    Phase B: single-shot K=128 fp16 mma.sync m16n8k16 (no mainloop barriers).
//    out = relu(x @ Wt + b)
// ---------------------------------------------------------------------------
#define SLD 136       // fp16 elems per smem row (128 + 8 pad) -> ldmatrix conflict-free
#define GEMM_SMEM (2 * 128 * SLD * (int)sizeof(__half))   // 69632 B

__device__ __forceinline__ void ldsm4(unsigned& r0, unsigned& r1, unsigned& r2, unsigned& r3,
                                      const __half* p) {
    unsigned a = (unsigned)__cvta_generic_to_shared(p);
    asm volatile("ldmatrix.sync.aligned.m8n8.x4.shared.b16 {%0,%1,%2,%3}, [%4];"
                 : "=r"(r0), "=r"(r1), "=r"(r2), "=r"(r3) : "r"(a));
}
__device__ __forceinline__ void ldsm4t(unsigned& r0, unsigned& r1, unsigned& r2, unsigned& r3,
                                       const __half* p) {
    unsigned a = (unsigned)__cvta_generic_to_shared(p);
    asm volatile("ldmatrix.sync.aligned.m8n8.x4.trans.shared.b16 {%0,%1,%2,%3}, [%4];"
                 : "=r"(r0), "=r"(r1), "=r"(r2), "=r"(r3) : "r"(a));
}
__device__ __forceinline__ void mma_fp16(
    float& c0, float& c1, float& c2, float& c3,
    unsigned a0, unsigned a1, unsigned a2, unsigned a3,
    unsigned b0, unsigned b1)
{
    asm volatile(
        "mma.sync.aligned.m16n8k16.row.col.f32.f16.f16.f32 "
        "{%0,%1,%2,%3}, {%4,%5,%6,%7}, {%8,%9}, {%0,%1,%2,%3};"
        : "+f"(c0), "+f"(c1), "+f"(c2), "+f"(c3)
        : "r"(a0), "r"(a1), "r"(a2), "r"(a3), "r"(b0), "r"(b1));
}

__global__ void __launch_bounds__(256, 2) fused_gather_gemm_kernel(
    const float* __restrict__ h, const float* __restrict__ b,
    float* __restrict__ out)
{
    extern __shared__ __half smem[];
    __half* Xs = smem;                 // 128 x SLD
    __half* Ws = smem + 128 * SLD;     // 128 x SLD

    const int tid  = threadIdx.x;
    const int wid  = tid >> 5;
    const int lane = tid & 31;
    const int warpM = wid & 3;
    const int warpN = wid >> 2;
    const int row0 = blockIdx.x * 128;
    const int qr = lane >> 2;
    const int qc = lane & 3;

    // ---- stage W (issues early; latency overlaps the gather below) ----
    {
        const int xm = tid >> 1;             // 0..127 (k row)
        const int xseg = (tid & 1) * 64;     // 64-fp16 segment
        const uint4* gw = reinterpret_cast<const uint4*>(&g_wt[xm * D + xseg]);
        #pragma unroll
        for (int q = 0; q < 8; q++)
            *reinterpret_cast<uint4*>(&Ws[xm * SLD + xseg + q * 8]) = __ldg(&gw[q]);
    }

    // ---- Phase A: gather 16 nodes per warp, write fp16 rows to Xs ----
    const float4* h4 = reinterpret_cast<const float4*>(h);
    #pragma unroll 1
    for (int t = 0; t < 16; t++) {
        const int lrow16 = wid * 16 + t;
        const int v = row0 + lrow16;
        uint2 u = make_uint2(0, 0);
        if (v < N_NODES) {
            int deg = g_cnt[v];
            int cap = min(deg, CAP);
            float4 acc = make_float4(0.f, 0.f, 0.f, 0.f);
            for (int base = 0; base < cap; base += 32) {
                int idx = base + lane;
                int2 ent = make_int2(0, 0);
                if (idx < cap) ent = __ldg(&g_bucket[v * CAP + idx]);
                int cnt = min(32, cap - base);
                #pragma unroll 4
                for (int j = 0; j < cnt; j++) {
                    int   sj = __shfl_sync(0xffffffffu, ent.x, j);
                    float wj = __int_as_float(__shfl_sync(0xffffffffu, ent.y, j));
                    float4 hv = __ldg(&h4[(size_t)sj * 32 + lane]);
                    acc.x = fmaf(wj, hv.x, acc.x);
                    acc.y = fmaf(wj, hv.y, acc.y);
                    acc.z = fmaf(wj, hv.z, acc.z);
                    acc.w = fmaf(wj, hv.w, acc.w);
                }
            }
            float degf = fmaxf((float)deg, 1.0f);
            float4 hv = __ldg(&h4[(size_t)v * 32 + lane]);
            __half2 pa = __floats2half2_rn(fmaf(degf, hv.x, acc.x), fmaf(degf, hv.y, acc.y));
            __half2 pb = __floats2half2_rn(fmaf(degf, hv.z, acc.z), fmaf(degf, hv.w, acc.w));
            u.x = *reinterpret_cast<unsigned*>(&pa);
            u.y = *reinterpret_cast<unsigned*>(&pb);
        }
        *reinterpret_cast<uint2*>(&Xs[lrow16 * SLD + lane * 4]) = u;
    }

    // accumulators, init with bias
    float acc[2][8][4];
    #pragma unroll
    for (int nj = 0; nj < 8; nj++) {
        int col = warpN * 64 + nj * 8 + qc * 2;
        float b0 = __ldg(&b[col]);
        float b1 = __ldg(&b[col + 1]);
        #pragma unroll
        for (int mi = 0; mi < 2; mi++) {
            acc[mi][nj][0] = b0; acc[mi][nj][1] = b1;
            acc[mi][nj][2] = b0; acc[mi][nj][3] = b1;
        }
    }

    const int lrow = (lane & 7) + ((lane >> 3) & 1) * 8;
    const int lk8  = (lane >> 4) * 8;

    __syncthreads();   // the only barrier

    // ---- Phase B: 8 barrier-free k-steps of ldmatrix + MMA ----
    #pragma unroll
    for (int ks = 0; ks < 8; ks++) {
        const int k0 = ks * 16;
        unsigned a[2][4];
        #pragma unroll
        for (int mi = 0; mi < 2; mi++)
            ldsm4(a[mi][0], a[mi][1], a[mi][2], a[mi][3],
                  &Xs[(warpM * 32 + mi * 16 + lrow) * SLD + k0 + lk8]);
        #pragma unroll
        for (int njp = 0; njp < 4; njp++) {
            const int n0 = warpN * 64 + njp * 16;
            unsigned bf[4];
            ldsm4t(bf[0], bf[1], bf[2], bf[3], &Ws[(k0 + lrow) * SLD + n0 + lk8]);
            const int nj0 = njp * 2, nj1 = njp * 2 + 1;
            #pragma unroll
            for (int mi = 0; mi < 2; mi++) {
                mma_fp16(acc[mi][nj0][0], acc[mi][nj0][1], acc[mi][nj0][2], acc[mi][nj0][3],
                         a[mi][0], a[mi][1], a[mi][2], a[mi][3], bf[0], bf[1]);
                mma_fp16(acc[mi][nj1][0], acc[mi][nj1][1], acc[mi][nj1][2], acc[mi][nj1][3],
                         a[mi][0], a[mi][1], a[mi][2], a[mi][3], bf[2], bf[3]);
            }
        }
    }

    // epilogue: relu + store
    #pragma unroll
    for (int mi = 0; mi < 2; mi++) {
        int rA = row0 + warpM * 32 + mi * 16 + qr;
        int rB = rA + 8;
        #pragma unroll
        for (int nj = 0; nj < 8; nj++) {
            int col = warpN * 64 + nj * 8 + qc * 2;
            if (rA < N_NODES) {
                float2 o;
                o.x = fmaxf(acc[mi][nj][0], 0.f);
                o.y = fmaxf(acc[mi][nj][1], 0.f);
                *reinterpret_cast<float2*>(&out[(size_t)rA * D + col]) = o;
            }
            if (rB < N_NODES) {
                float2 o;
                o.x = fmaxf(acc[mi][nj][2], 0.f);
                o.y = fmaxf(acc[mi][nj][3], 0.f);
                *reinterpret_cast<float2*>(&out[(size_t)rB * D + col]) = o;
            }
        }
    }
}

// ---------------------------------------------------------------------------
extern "C" void kernel_launch(void* const* d_in, const int* in_sizes, int n_in,
                              void* d_out, int out_size)
{
    const float* h   = (const float*)d_in[0];
    const float* d   = (const float*)d_in[1];
    const int*   src = (const int*)d_in[2];
    const int*   dst = (const int*)d_in[3];
    const float* W   = (const float*)d_in[4];
    const float* b   = (const float*)d_in[5];
    float* out = (float*)d_out;

    // dynamic smem opt-in (host attribute set; idempotent, not a stream op)
    cudaFuncSetAttribute(fused_gather_gemm_kernel,
                         cudaFuncAttributeMaxDynamicSharedMemorySize, GEMM_SMEM);

    prep_kernel<<<256, 256>>>(W);
    fill_kernel<<<(N_EDGES / 4 + 255) / 256, 256>>>(d, src, dst);
    fused_gather_gemm_kernel<<<(N_NODES + 127) / 128, 256, GEMM_SMEM>>>(h, b, out);
}